// round 17
// baseline (speedup 1.0000x reference)
#include <cuda_runtime.h>
#include <cuda_bf16.h>
#include <cstdint>

// ---------------------------------------------------------------------------
// Problem constants
// ---------------------------------------------------------------------------
#define BB 2
#define LL 2048
#define DD 1024
#define HH 16
#define HD 64
#define BL (BB*LL)           // 4096
#define EPS 1e-6f

// ---------------------------------------------------------------------------
// Scratch
// ---------------------------------------------------------------------------
__device__ float g_cp [BL*3*DD];           // PLANAR: [scale | shift | gate] per row
__device__ float g_xm [BL*DD];             // modulated x, tf32-rounded
__device__ float g_qkv[BL*3*DD];
__device__ float g_q  [BL*DD];             // [B,H,L,HD], x0.125, tf32-rounded
__device__ float g_k  [BL*DD];             // [B,H,L,HD], tf32-rounded
__device__ float g_v  [BL*DD];             // [B,H,L,HD], tf32-rounded
__device__ float g_att[BL*DD];             // attn out [B,L,D], tf32-rounded
__device__ float g_cr [BL*DD];             // cond, tf32-rounded
__device__ float g_wc [DD*3*DD];           // W_cond, tf32-rounded, columns planar-permuted
__device__ float g_wq [DD*3*DD];           // W_qkv, tf32-rounded
__device__ float g_wo [DD*DD];             // W_out, tf32-rounded

// ---------------------------------------------------------------------------
// helpers
// ---------------------------------------------------------------------------
__device__ __forceinline__ float to_tf32(float x) {
    uint32_t r;
    asm("cvt.rna.tf32.f32 %0, %1;" : "=r"(r) : "f"(x));
    return __uint_as_float(r);
}

__device__ __forceinline__ void mma_tf32(float acc[4],
                                         uint32_t a0, uint32_t a1, uint32_t a2, uint32_t a3,
                                         uint32_t b0, uint32_t b1) {
    asm volatile(
        "mma.sync.aligned.m16n8k8.row.col.f32.tf32.tf32.f32 "
        "{%0,%1,%2,%3}, {%4,%5,%6,%7}, {%8,%9}, {%0,%1,%2,%3};\n"
        : "+f"(acc[0]), "+f"(acc[1]), "+f"(acc[2]), "+f"(acc[3])
        : "r"(a0), "r"(a1), "r"(a2), "r"(a3), "r"(b0), "r"(b1));
}

__device__ __forceinline__ uint32_t smem_u32(const void* p) {
    return (uint32_t)__cvta_generic_to_shared(p);
}

#define CP_ASYNC16(dst_u32, src_ptr) \
    asm volatile("cp.async.cg.shared.global [%0], [%1], 16;\n" \
                 :: "r"(dst_u32), "l"(src_ptr))
#define CP_COMMIT() asm volatile("cp.async.commit_group;\n")
#define CP_WAIT1()  asm volatile("cp.async.wait_group 1;\n")
#define CP_WAIT0()  asm volatile("cp.async.wait_group 0;\n")

// GEMM smem sizing (BM=128, BN=128, BK=32, 3 stages)
#define G_BK    32
#define G_NST   3
#define G_ASTR  (G_BK + 4)          // 36
#define G_BSTR  (128 + 8)           // 136
#define G_ASZ   (128 * G_ASTR)      // 4608 floats
#define G_BSZ   (G_BK * G_BSTR)     // 4352 floats
#define MMA_SMEM_BYTES ((G_NST * (G_ASZ + G_BSZ)) * (int)sizeof(float))  // 107520

// ---------------------------------------------------------------------------
// Fused tf32 pre-round. W_cond columns permuted to planar: col 3d+s -> s*D+d
// ---------------------------------------------------------------------------
#define R_C0 ((long)BL*DD/4)
#define R_C1 (R_C0 + (long)DD*3*DD/4)
#define R_C2 (R_C1 + (long)DD*3*DD/4)
#define R_C3 (R_C2 + (long)DD*DD/4)

__global__ void round_all(const float* __restrict__ cond, const float* __restrict__ Wc,
                          const float* __restrict__ Wq, const float* __restrict__ Wo,
                          float* __restrict__ cr, float* __restrict__ wc,
                          float* __restrict__ wq, float* __restrict__ wo)
{
    const long idx = (long)blockIdx.x * blockDim.x + threadIdx.x;
    if (idx < R_C0) {
        float4 v = ((const float4*)cond)[idx];
        v.x = to_tf32(v.x); v.y = to_tf32(v.y);
        v.z = to_tf32(v.z); v.w = to_tf32(v.w);
        ((float4*)cr)[idx] = v;
    } else if (idx < R_C1) {
        const long i = idx - R_C0;
        const int k  = (int)(i / (3 * DD / 4));
        const int j4 = (int)(i % (3 * DD / 4)) * 4;
        float4 v = ((const float4*)Wc)[i];
        float vals[4] = {v.x, v.y, v.z, v.w};
#pragma unroll
        for (int e = 0; e < 4; e++) {
            const int c = j4 + e;
            const int d = c / 3;
            const int s = c - d * 3;
            wc[(long)k * 3 * DD + s * DD + d] = to_tf32(vals[e]);
        }
    } else if (idx < R_C2) {
        const long i = idx - R_C1;
        float4 v = ((const float4*)Wq)[i];
        v.x = to_tf32(v.x); v.y = to_tf32(v.y);
        v.z = to_tf32(v.z); v.w = to_tf32(v.w);
        ((float4*)wq)[i] = v;
    } else {
        const long i = idx - R_C2;
        float4 v = ((const float4*)Wo)[i];
        v.x = to_tf32(v.x); v.y = to_tf32(v.y);
        v.z = to_tf32(v.z); v.w = to_tf32(v.w);
        ((float4*)wo)[i] = v;
    }
}

// ---------------------------------------------------------------------------
// Batched tf32 tensor-core GEMM (NN), BK=32, 3-stage cp.async pipeline,
// wait_group(1): each prefetch gets TWO compute phases to land.
//   At iter it: commits so far = 2 + it; wait(1) => stage it resident.
//   Prefetch stage it+2 into buf (it+2)%3 (last read at compute it-1; all
//   warps past it via the barrier).  ONE __syncthreads per K-tile.
// EPI: C += residual + gate (planar cp, coalesced float2).
// ---------------------------------------------------------------------------
template<int BM, int BN, bool EPI>
__global__ void __launch_bounds__(256)
mma_gemm(const float* __restrict__ A, const float* __restrict__ Bg,
         float* __restrict__ C,
         int K, int lda, int ldb, int ldc,
         long sA, long sB, int zmod, long sC_hi, long sC_lo,
         const float* __restrict__ Rres, const float* __restrict__ Gg)
{
    constexpr int BK = G_BK;
    constexpr int NST = G_NST;
    constexpr int WM = BM / 2;
    constexpr int WN = BN / 4;
    constexpr int MA = WM / 16;
    constexpr int NA = WN / 8;
    constexpr int ASTR = G_ASTR;
    constexpr int BSTR = BN + 8;
    constexpr int ASZ = BM * ASTR;
    constexpr int BSZ = BK * BSTR;

    extern __shared__ float gsm[];
    float* As = gsm;                     // NST * ASZ
    float* Bs = gsm + NST * ASZ;         // NST * BSZ

    const int z = blockIdx.z;
    A += (long)z * sA;
    Bg += (long)z * sB;
    C += (long)(z / zmod) * sC_hi + (long)(z % zmod) * sC_lo;

    const int bm = blockIdx.y * BM;
    const int bn = blockIdx.x * BN;
    const int tid = threadIdx.x;
    const int lane = tid & 31;
    const int warp = tid >> 5;
    const int wm = warp >> 2;
    const int wn = warp & 3;
    const int g  = lane >> 2;
    const int tg = lane & 3;

    constexpr int A_IT = BM * BK / 1024;          // 4
    constexpr int A_RSTEP = 1024 / BK;            // 32
    const int arow = tid / (BK / 4);              // tid/8
    const int acol = (tid % (BK / 4)) * 4;
    constexpr int B_IT = BK * BN / 1024;          // 4
    constexpr int B_RSTEP = 1024 / BN;            // 8
    const int brow = tid / (BN / 4);              // tid/32
    const int bcol = (tid % (BN / 4)) * 4;

    float acc[MA][NA][4];
#pragma unroll
    for (int i = 0; i < MA; i++)
#pragma unroll
        for (int j = 0; j < NA; j++)
#pragma unroll
            for (int c = 0; c < 4; c++) acc[i][j][c] = 0.f;

    const int nk = K / BK;

    // prologue: fill stages 0 and 1
#pragma unroll
    for (int s = 0; s < NST - 1; s++) {
        if (s < nk) {
            float* dA = As + s * ASZ;
            float* dB = Bs + s * BSZ;
            const long k0 = (long)s * BK;
#pragma unroll
            for (int i = 0; i < A_IT; i++)
                CP_ASYNC16(smem_u32(&dA[(arow + i * A_RSTEP) * ASTR + acol]),
                           &A[(long)(bm + arow + i * A_RSTEP) * lda + k0 + acol]);
#pragma unroll
            for (int i = 0; i < B_IT; i++)
                CP_ASYNC16(smem_u32(&dB[(brow + i * B_RSTEP) * BSTR + bcol]),
                           &Bg[(k0 + brow + i * B_RSTEP) * ldb + bn + bcol]);
        }
        CP_COMMIT();
    }

    for (int it = 0; it < nk; it++) {
        CP_WAIT1();            // stage `it` resident (newest commit may fly)
        __syncthreads();       // all warps done computing iter it-1

        // prefetch stage it+2 into buffer (it+2)%3
        const int t = it + 2;
        if (t < nk) {
            const int fb = t % NST;
            float* dA = As + fb * ASZ;
            float* dB = Bs + fb * BSZ;
            const long k0 = (long)t * BK;
#pragma unroll
            for (int i = 0; i < A_IT; i++)
                CP_ASYNC16(smem_u32(&dA[(arow + i * A_RSTEP) * ASTR + acol]),
                           &A[(long)(bm + arow + i * A_RSTEP) * lda + k0 + acol]);
#pragma unroll
            for (int i = 0; i < B_IT; i++)
                CP_ASYNC16(smem_u32(&dB[(brow + i * B_RSTEP) * BSTR + bcol]),
                           &Bg[(k0 + brow + i * B_RSTEP) * ldb + bn + bcol]);
        }
        CP_COMMIT();           // unconditional: keeps wait_group accounting

        const int buf = it % NST;
        const float* cA = As + buf * ASZ;
        const float* cB = Bs + buf * BSZ;

#pragma unroll
        for (int ks = 0; ks < 4; ks++) {
            uint32_t af[MA][4], bf[NA][2];
#pragma unroll
            for (int i = 0; i < MA; i++) {
                const int r0 = (wm * WM + i * 16 + g) * ASTR + ks * 8 + tg;
                const int r1 = r0 + 8 * ASTR;
                af[i][0] = __float_as_uint(cA[r0]);
                af[i][1] = __float_as_uint(cA[r1]);
                af[i][2] = __float_as_uint(cA[r0 + 4]);
                af[i][3] = __float_as_uint(cA[r1 + 4]);
            }
#pragma unroll
            for (int j = 0; j < NA; j++) {
                const int c0 = (ks * 8 + tg) * BSTR + wn * WN + j * 8 + g;
                bf[j][0] = __float_as_uint(cB[c0]);
                bf[j][1] = __float_as_uint(cB[c0 + 4 * BSTR]);
            }
#pragma unroll
            for (int i = 0; i < MA; i++)
#pragma unroll
                for (int j = 0; j < NA; j++)
                    mma_tf32(acc[i][j], af[i][0], af[i][1], af[i][2], af[i][3],
                             bf[j][0], bf[j][1]);
        }
    }

#pragma unroll
    for (int i = 0; i < MA; i++) {
        const int r0 = bm + wm * WM + i * 16 + g;
#pragma unroll
        for (int j = 0; j < NA; j++) {
            const int c = bn + wn * WN + j * 8 + tg * 2;
            float2 v0 = make_float2(acc[i][j][0], acc[i][j][1]);
            float2 v1 = make_float2(acc[i][j][2], acc[i][j][3]);
            if (EPI) {
                const float2 rr0 = *reinterpret_cast<const float2*>(&Rres[(long)r0 * DD + c]);
                const float2 rr1 = *reinterpret_cast<const float2*>(&Rres[(long)(r0 + 8) * DD + c]);
                const float2 gg0 = *reinterpret_cast<const float2*>(&Gg[(long)r0 * 3 * DD + 2 * DD + c]);
                const float2 gg1 = *reinterpret_cast<const float2*>(&Gg[(long)(r0 + 8) * 3 * DD + 2 * DD + c]);
                v0.x += rr0.x + gg0.x;  v0.y += rr0.y + gg0.y;
                v1.x += rr1.x + gg1.x;  v1.y += rr1.y + gg1.y;
            }
            *reinterpret_cast<float2*>(&C[(long)r0 * ldc + c]) = v0;
            *reinterpret_cast<float2*>(&C[(long)(r0 + 8) * ldc + c]) = v1;
        }
    }
}

// ---------------------------------------------------------------------------
// Flash attention v4 (verified R14/R16; unchanged)
// ---------------------------------------------------------------------------
#define F3_QSTR 68
#define F3_KSTR 76
#define F3_VSTR 72
#define F3_SQSZ (128 * F3_QSTR)
#define F3_KSZ  (64 * F3_KSTR)
#define F3_VSZ  (64 * F3_VSTR)
#define F3_KVSZ (F3_KSZ + F3_VSZ)
#define F3_TOT  (F3_SQSZ + 2 * F3_KVSZ)

__global__ void __launch_bounds__(256, 2)
flash_kernel(const float* __restrict__ q, const float* __restrict__ k,
             const float* __restrict__ v, float* __restrict__ att)
{
    extern __shared__ float sm[];
    float* sQ = sm;

    const int tid = threadIdx.x;
    const int lane = tid & 31;
    const int warp = tid >> 5;
    const int g  = lane >> 2;
    const int tg = lane & 3;

    const int frow = tid >> 2;
    const int fc0  = (tid & 3) * 4;

    const int qrow = (warp * 16 + g) * F3_QSTR;
    const int srcA = (lane & ~3) | (tg >> 1);
    const int srcB = srcA + 2;
    const bool esel = (tg & 1);

    for (int rep = 0; rep < 2; rep++) {
        const int tt = blockIdx.x + rep * 256;
        const int bh = tt >> 4;
        const int b  = bh >> 4;
        const int h  = bh & (HH - 1);
        const int m0 = (tt & 15) * 128;

        const float* qbase = q + ((long)bh * LL + m0) * HD;
        const float* kbase = k + (long)bh * LL * HD;
        const float* vbase = v + (long)bh * LL * HD;

        __syncthreads();

        for (int i = tid; i < 128 * 16; i += 256) {
            const int r = i >> 4, c4 = (i & 15) * 4;
            *reinterpret_cast<float4*>(&sQ[r * F3_QSTR + c4]) =
                *reinterpret_cast<const float4*>(&qbase[(long)r * HD + c4]);
        }

        {
            float* dK = sm + F3_SQSZ;
            float* dV = dK + F3_KSZ;
#pragma unroll
            for (int c = 0; c < 4; c++) {
                const int col = fc0 + c * 16;
                CP_ASYNC16(smem_u32(&dK[frow * F3_KSTR + col]),
                           &kbase[(long)frow * HD + col]);
                CP_ASYNC16(smem_u32(&dV[frow * F3_VSTR + col]),
                           &vbase[(long)frow * HD + col]);
            }
            CP_COMMIT();
        }

        float accO[8][4];
#pragma unroll
        for (int j = 0; j < 8; j++)
#pragma unroll
            for (int c = 0; c < 4; c++) accO[j][c] = 0.f;
        float mrow0 = -1e30f, mrow1 = -1e30f, lrow0 = 0.f, lrow1 = 0.f;

        for (int it = 0; it < 32; it++) {
            CP_WAIT0();
            __syncthreads();

            if (it + 1 < 32) {
                const int j0n = (it + 1) * 64;
                float* dK = sm + F3_SQSZ + ((it + 1) & 1) * F3_KVSZ;
                float* dV = dK + F3_KSZ;
#pragma unroll
                for (int c = 0; c < 4; c++) {
                    const int col = fc0 + c * 16;
                    CP_ASYNC16(smem_u32(&dK[frow * F3_KSTR + col]),
                               &kbase[(long)(j0n + frow) * HD + col]);
                    CP_ASYNC16(smem_u32(&dV[frow * F3_VSTR + col]),
                               &vbase[(long)(j0n + frow) * HD + col]);
                }
            }
            CP_COMMIT();

            const float* sK = sm + F3_SQSZ + (it & 1) * F3_KVSZ;
            const float* sV = sK + F3_KSZ;

            float s[8][4];
#pragma unroll
            for (int j = 0; j < 8; j++)
#pragma unroll
                for (int c = 0; c < 4; c++) s[j][c] = 0.f;
#pragma unroll
            for (int ks = 0; ks < 8; ks++) {
                const int r0 = qrow + ks * 8 + tg;
                const uint32_t a0 = __float_as_uint(sQ[r0]);
                const uint32_t a1 = __float_as_uint(sQ[r0 + 8 * F3_QSTR]);
                const uint32_t a2 = __float_as_uint(sQ[r0 + 4]);
                const uint32_t a3 = __float_as_uint(sQ[r0 + 8 * F3_QSTR + 4]);
#pragma unroll
                for (int j = 0; j < 8; j++) {
                    const int c0 = (j * 8 + g) * F3_KSTR + ks * 8 + tg;
                    mma_tf32(s[j], a0, a1, a2, a3,
                             __float_as_uint(sK[c0]),
                             __float_as_uint(sK[c0 + 4]));
                }
            }

            float mx0 = -1e30f, mx1 = -1e30f;
#pragma unroll
            for (int j = 0; j < 8; j++) {
                mx0 = fmaxf(mx0, fmaxf(s[j][0], s[j][1]));
                mx1 = fmaxf(mx1, fmaxf(s[j][2], s[j][3]));
            }
            mx0 = fmaxf(mx0, __shfl_xor_sync(~0u, mx0, 1));
            mx0 = fmaxf(mx0, __shfl_xor_sync(~0u, mx0, 2));
            mx1 = fmaxf(mx1, __shfl_xor_sync(~0u, mx1, 1));
            mx1 = fmaxf(mx1, __shfl_xor_sync(~0u, mx1, 2));

            const float mn0 = fmaxf(mrow0, mx0);
            const float mn1 = fmaxf(mrow1, mx1);
            const float al0 = __expf(mrow0 - mn0);
            const float al1 = __expf(mrow1 - mn1);
            mrow0 = mn0; mrow1 = mn1;

            float ps0 = 0.f, ps1 = 0.f;
#pragma unroll
            for (int j = 0; j < 8; j++) {
                s[j][0] = __expf(s[j][0] - mn0);
                s[j][1] = __expf(s[j][1] - mn0);
                s[j][2] = __expf(s[j][2] - mn1);
                s[j][3] = __expf(s[j][3] - mn1);
                ps0 += s[j][0] + s[j][1];
                ps1 += s[j][2] + s[j][3];
            }
            ps0 += __shfl_xor_sync(~0u, ps0, 1);
            ps0 += __shfl_xor_sync(~0u, ps0, 2);
            ps1 += __shfl_xor_sync(~0u, ps1, 1);
            ps1 += __shfl_xor_sync(~0u, ps1, 2);
            lrow0 = lrow0 * al0 + ps0;
            lrow1 = lrow1 * al1 + ps1;

#pragma unroll
            for (int j = 0; j < 8; j++) {
                accO[j][0] *= al0; accO[j][1] *= al0;
                accO[j][2] *= al1; accO[j][3] *= al1;
            }

#pragma unroll
            for (int j = 0; j < 8; j++) {
                s[j][0] = to_tf32(s[j][0]);
                s[j][1] = to_tf32(s[j][1]);
                s[j][2] = to_tf32(s[j][2]);
                s[j][3] = to_tf32(s[j][3]);
            }

#pragma unroll
            for (int ks = 0; ks < 8; ks++) {
                const float p0A = __shfl_sync(~0u, s[ks][0], srcA);
                const float p1A = __shfl_sync(~0u, s[ks][1], srcA);
                const float p2A = __shfl_sync(~0u, s[ks][2], srcA);
                const float p3A = __shfl_sync(~0u, s[ks][3], srcA);
                const float p0B = __shfl_sync(~0u, s[ks][0], srcB);
                const float p1B = __shfl_sync(~0u, s[ks][1], srcB);
                const float p2B = __shfl_sync(~0u, s[ks][2], srcB);
                const float p3B = __shfl_sync(~0u, s[ks][3], srcB);
                const uint32_t a0 = __float_as_uint(esel ? p1A : p0A);
                const uint32_t a1 = __float_as_uint(esel ? p3A : p2A);
                const uint32_t a2 = __float_as_uint(esel ? p1B : p0B);
                const uint32_t a3 = __float_as_uint(esel ? p3B : p2B);
#pragma unroll
                for (int j = 0; j < 8; j++) {
                    const int c0 = (ks * 8 + tg) * F3_VSTR + j * 8 + g;
                    mma_tf32(accO[j], a0, a1, a2, a3,
                             __float_as_uint(sV[c0]),
                             __float_as_uint(sV[c0 + 4 * F3_VSTR]));
                }
            }
        }

        const float inv0 = 1.f / lrow0;
        const float inv1 = 1.f / lrow1;
        float* obase = att + ((long)(b * LL + m0 + warp * 16 + g)) * DD + h * HD;
#pragma unroll
        for (int j = 0; j < 8; j++) {
            const int c = j * 8 + tg * 2;
            *reinterpret_cast<float2*>(&obase[c]) =
                make_float2(to_tf32(accO[j][0] * inv0), to_tf32(accO[j][1] * inv0));
            *reinterpret_cast<float2*>(&obase[(long)8 * DD + c]) =
                make_float2(to_tf32(accO[j][2] * inv1), to_tf32(accO[j][3] * inv1));
        }
    }
}

// ---------------------------------------------------------------------------
// Fused RMSNorm + AdaLN modulation: one block per row.
//   xn = x * rinv * rms_scale  (same op order as before, bit-identical)
//   xm = to_tf32(xn * (1 + scale) + shift)   (planar cp)
// Eliminates the 32 MB xn round-trip and one launch.
// ---------------------------------------------------------------------------
__global__ void norm_modulate_kernel(const float* __restrict__ x,
                                     const float* __restrict__ scale,
                                     const float* __restrict__ cp,
                                     float* __restrict__ xm)
{
    const int row = blockIdx.x;
    const float4 a = *((const float4*)(x + (long)row * DD) + threadIdx.x);
    float ss = a.x * a.x + a.y * a.y + a.z * a.z + a.w * a.w;

    __shared__ float red[8];
    for (int o = 16; o > 0; o >>= 1) ss += __shfl_xor_sync(~0u, ss, o);
    if ((threadIdx.x & 31) == 0) red[threadIdx.x >> 5] = ss;
    __syncthreads();
    __shared__ float rinv_s;
    if (threadIdx.x == 0) {
        float t = 0.f;
#pragma unroll
        for (int i = 0; i < 8; i++) t += red[i];
        rinv_s = rsqrtf(t * (1.0f / DD) + EPS);
    }
    __syncthreads();
    const float rinv = rinv_s;

    const int d4 = threadIdx.x * 4;
    const float4 sc4 = *((const float4*)scale + threadIdx.x);
    const long base = (long)row * 3 * DD + d4;
    const float4 mo = *reinterpret_cast<const float4*>(&cp[base]);
    const float4 sh = *reinterpret_cast<const float4*>(&cp[base + DD]);

    float4 o;
    o.x = to_tf32((a.x * rinv * sc4.x) * (1.f + mo.x) + sh.x);
    o.y = to_tf32((a.y * rinv * sc4.y) * (1.f + mo.y) + sh.y);
    o.z = to_tf32((a.z * rinv * sc4.z) * (1.f + mo.z) + sh.z);
    o.w = to_tf32((a.w * rinv * sc4.w) * (1.f + mo.w) + sh.w);
    *reinterpret_cast<float4*>(&xm[(long)row * DD + d4]) = o;
}

// ---------------------------------------------------------------------------
// RoPE + head scatter — all outputs [B,H,L,HD], coalesced, tf32-rounded
// ---------------------------------------------------------------------------
__global__ void rope_kernel(const float* __restrict__ qkv,
                            const float* __restrict__ pos,
                            float* __restrict__ q,
                            float* __restrict__ k,
                            float* __restrict__ v)
{
    const int bl = blockIdx.x;
    const int b = bl >> 11;
    const int l = bl & (LL - 1);
    __shared__ float srow[3 * DD];
    __shared__ float spos[2 * HD];

    const float4* src = (const float4*)(qkv + (long)bl * (3 * DD));
    for (int i = threadIdx.x; i < (3 * DD) / 4; i += blockDim.x)
        ((float4*)srow)[i] = src[i];
    if (threadIdx.x < (2 * HD) / 4)
        ((float4*)spos)[threadIdx.x] =
            ((const float4*)(pos + (long)bl * (2 * HD)))[threadIdx.x];
    __syncthreads();

    for (int idx = threadIdx.x; idx < DD; idx += blockDim.x) {
        const int h = idx >> 6;
        const int d = idx & (HD - 1);
        const int c = (d * HH + h) * 3;
        const int dp = (d < HD / 2) ? d + HD / 2 : d - HD / 2;
        const int c2 = (dp * HH + h) * 3;
        const float sgn = (d < HD / 2) ? -1.f : 1.f;
        const float s = spos[2 * d];
        const float ct = spos[2 * d + 1];

        const float qo = srow[c] * ct + sgn * srow[c2] * s;
        const float ko = srow[c + 1] * ct + sgn * srow[c2 + 1] * s;

        const long o = ((long)(b * HH + h) * LL + l) * HD + d;
        q[o] = to_tf32(qo * 0.125f);
        k[o] = to_tf32(ko);
        v[o] = to_tf32(srow[c + 2]);
    }
}

// ---------------------------------------------------------------------------
// Launch
// ---------------------------------------------------------------------------
extern "C" void kernel_launch(void* const* d_in, const int* in_sizes, int n_in,
                              void* d_out, int out_size)
{
    const float* x         = (const float*)d_in[0];
    const float* cond      = (const float*)d_in[1];
    const float* pos       = (const float*)d_in[2];
    const float* rms_scale = (const float*)d_in[3];
    const float* W_cond    = (const float*)d_in[4];
    const float* W_qkv     = (const float*)d_in[5];
    const float* W_out     = (const float*)d_in[6];
    float* out = (float*)d_out;

    float *cp, *xm, *qkv, *q, *k, *v, *att, *cr, *wc, *wq, *wo;
    cudaGetSymbolAddress((void**)&cp,  g_cp);
    cudaGetSymbolAddress((void**)&xm,  g_xm);
    cudaGetSymbolAddress((void**)&qkv, g_qkv);
    cudaGetSymbolAddress((void**)&q,   g_q);
    cudaGetSymbolAddress((void**)&k,   g_k);
    cudaGetSymbolAddress((void**)&v,   g_v);
    cudaGetSymbolAddress((void**)&att, g_att);
    cudaGetSymbolAddress((void**)&cr,  g_cr);
    cudaGetSymbolAddress((void**)&wc,  g_wc);
    cudaGetSymbolAddress((void**)&wq,  g_wq);
    cudaGetSymbolAddress((void**)&wo,  g_wo);

    static bool attr_set = false;
    if (!attr_set) {
        cudaFuncSetAttribute(flash_kernel,
                             cudaFuncAttributeMaxDynamicSharedMemorySize,
                             F3_TOT * sizeof(float));
        cudaFuncSetAttribute(mma_gemm<128, 128, false>,
                             cudaFuncAttributeMaxDynamicSharedMemorySize,
                             MMA_SMEM_BYTES);
        cudaFuncSetAttribute(mma_gemm<128, 128, true>,
                             cudaFuncAttributeMaxDynamicSharedMemorySize,
                             MMA_SMEM_BYTES);
        attr_set = true;
    }

    // 0. fused tf32 pre-round (cond + weights; W_cond columns planar-permuted)
    round_all<<<(int)(R_C3 / 256), 256>>>(cond, W_cond, W_qkv, W_out,
                                          cr, wc, wq, wo);

    // 1. cond projection (-> planar cp)
    mma_gemm<128, 128, false><<<dim3(24, 32, 1), 256, MMA_SMEM_BYTES>>>(
        cr, wc, cp, DD, DD, 3 * DD, 3 * DD,
        0, 0, 1, 0, 0, nullptr, nullptr);

    // 2. fused RMSNorm + modulate
    norm_modulate_kernel<<<BL, 256>>>(x, rms_scale, cp, xm);

    // 3. qkv projection
    mma_gemm<128, 128, false><<<dim3(24, 32, 1), 256, MMA_SMEM_BYTES>>>(
        xm, wq, qkv, DD, DD, 3 * DD, 3 * DD,
        0, 0, 1, 0, 0, nullptr, nullptr);

    // 4. RoPE + head scatter
    rope_kernel<<<BL, 256>>>(qkv, pos, q, k, v);

    // 5. flash attention v4 (persistent, one wave) -> att [B,L,D]
    flash_kernel<<<256, 256, F3_TOT * sizeof(float)>>>(q, k, v, att);

    // 6. out projection + residual + gate (planar gate)
    mma_gemm<128, 128, true><<<dim3(8, 32, 1), 256, MMA_SMEM_BYTES>>>(
        att, wo, out, DD, DD, DD, DD,
        0, 0, 1, 0, 0, x, cp);
}